// round 2
// baseline (speedup 1.0000x reference)
#include <cuda_runtime.h>
#include <cstdint>
#include <cstddef>

#define N_VOX   200000
#define C_IN    128
#define D_MODEL 128
#define NY      400
#define NX      400
#define NB      4
#define PLANE   (NY*NX)        /* 160000 */
#define NPOS    (NB*PLANE)     /* 640000 */

typedef unsigned long long u64;

// ---- scratch (device globals; float4/int4 typing guarantees 16B alignment) ----
__device__ float4 g_feat4[(size_t)N_VOX * (D_MODEL/4)];   // 102.4 MB
__device__ float4 g_WT4[C_IN * (D_MODEL/4)];              // 64 KB: W0^T  [k][d]
__device__ int4   g_inv4[NPOS/4];                          // 2.56 MB inverse map
__device__ int    g_is64;                                  // coors dtype flag

#define g_feat ((float*)g_feat4)
#define g_WT   ((float*)g_WT4)
#define g_inv  ((int*)g_inv4)

// ---- packed fp32 FMA (FFMA2; PTX-only per SASS_QUICKREF) ----
__device__ __forceinline__ void fma2(u64 &d, u64 a, u64 b) {
    asm("fma.rn.f32x2 %0, %1, %2, %0;" : "+l"(d) : "l"(a), "l"(b));
}
union F2U { float2 f2; float f[2]; u64 u; };

// ---- kernel 1: transpose W0 [D][K] -> g_WT [K][D] ----
__global__ void k_transpose_w(const float* __restrict__ W0) {
    int idx = blockIdx.x * 256 + threadIdx.x;   // 16384 exactly
    int d = idx >> 7, k = idx & 127;
    g_WT[k * D_MODEL + d] = W0[idx];
}

// ---- kernel 2: init inverse map to -1 ----
__global__ void k_init_inv() {
    int idx = blockIdx.x * 256 + threadIdx.x;   // 160000 int4 exactly (625 blocks)
    g_inv4[idx] = make_int4(-1, -1, -1, -1);
}

// ---- kernel 2b: detect coors dtype (int64 vs int32), pure function of input ----
// int64 layout as 32-bit words: [b,0, 0,0, y,0, x,0] -> all odd words zero.
// int32 layout: [b, z(=0), y, x] -> words 8i+3 / 8i+7 are random x values.
__global__ void k_detect(const int* __restrict__ c32) {
    if (threadIdx.x == 0) {
        int acc = 0;
        for (int i = 0; i < 128; i++) acc |= c32[8*i + 3] | c32[8*i + 7];
        g_is64 = (acc == 0) ? 1 : 0;
    }
}

// ---- kernel 3: scatter voxel index into inverse map ----
__global__ void k_scatter(const int* __restrict__ c32) {
    int n = blockIdx.x * 256 + threadIdx.x;
    if (n >= N_VOX) return;
    int b, y, x;
    if (g_is64) {             // values < 2^31: low words suffice
        b = c32[8*n + 0]; y = c32[8*n + 4]; x = c32[8*n + 6];
    } else {
        b = c32[4*n + 0]; y = c32[4*n + 2]; x = c32[4*n + 3];
    }
    g_inv[b * PLANE + y * NX + x] = n;
}

// ---- kernel 4: GEMM  feat = V @ W0^T + b0  (f32x2 packed FMA) ----
// 256 thr (8 warps), BM=64 rows/block, full N=128, K=128.
// Warp w owns columns [16w,16w+16); lane l owns rows {l, l+32}.
// A: smem stride-129 (conflict-free scalar LDS). B: warp-uniform LDG.128 from
// g_WT (64KB, L1-resident) -- 1 wavefront each, overlapped with FMA pipe.
#define BM 64
#define VS_STRIDE 129
__global__ __launch_bounds__(256) void k_gemm(const float* __restrict__ V,
                                              const float* __restrict__ b0) {
    __shared__ float Vs[BM * VS_STRIDE];        // 33 KB static
    int tid = threadIdx.x;
    int row_base = blockIdx.x * BM;             // 200000 = 64*3125, no guards

    #pragma unroll
    for (int i = 0; i < 32; i++) {
        int lin = tid + 256 * i;                // 8192 floats
        int r = lin >> 7, k = lin & 127;
        Vs[r * VS_STRIDE + k] = V[(size_t)(row_base + r) * C_IN + k];
    }
    __syncthreads();

    int w = tid >> 5, l = tid & 31;
    u64 acc[2][8];
    const float2* b2 = (const float2*)b0;
    #pragma unroll
    for (int j = 0; j < 8; j++) {
        F2U t; t.f2 = b2[w * 8 + j];
        acc[0][j] = t.u; acc[1][j] = t.u;
    }

    const float4* Wg = g_WT4 + w * 4;           // row k: 32 float4; warp-uniform
    #pragma unroll 4
    for (int k = 0; k < 128; k++) {
        union { float4 f4; u64 u[2]; } q0, q1, q2, q3;
        q0.f4 = Wg[k * 32 + 0];
        q1.f4 = Wg[k * 32 + 1];
        q2.f4 = Wg[k * 32 + 2];
        q3.f4 = Wg[k * 32 + 3];
        float a0 = Vs[l * VS_STRIDE + k];
        float a1 = Vs[(l + 32) * VS_STRIDE + k];
        F2U d0; d0.f[0] = a0; d0.f[1] = a0;
        F2U d1; d1.f[0] = a1; d1.f[1] = a1;
        u64 bb[8] = { q0.u[0], q0.u[1], q1.u[0], q1.u[1],
                      q2.u[0], q2.u[1], q3.u[0], q3.u[1] };
        #pragma unroll
        for (int j = 0; j < 8; j++) {
            fma2(acc[0][j], d0.u, bb[j]);
            fma2(acc[1][j], d1.u, bb[j]);
        }
    }

    // epilogue: 4x STG.128 per lane-row (64B contiguous, sector-perfect)
    #pragma unroll
    for (int r = 0; r < 2; r++) {
        int row = row_base + l + 32 * r;
        float4* dst = g_feat4 + (size_t)row * (D_MODEL/4) + w * 4;
        #pragma unroll
        for (int j = 0; j < 4; j++) {
            union { float4 f4; u64 u[2]; } o;
            o.u[0] = acc[r][2*j];
            o.u[1] = acc[r][2*j + 1];
            dst[j] = o.f4;
        }
    }
}

// ---- kernel 5: gather + transpose into [B, C, NY, NX] ----
// Block = 32 consecutive flat positions (160000 % 32 == 0: never crosses batch).
// feat rows read coalesced; stride-129 smem transpose (conflict-free both
// phases); output writes fully coalesced (also serves as zero-init).
__global__ __launch_bounds__(256) void k_gather(float* __restrict__ out) {
    __shared__ int   s_inv[32];
    __shared__ float tile[32 * 129];
    int base = blockIdx.x * 32;
    int tid = threadIdx.x;
    if (tid < 32) s_inv[tid] = g_inv[base + tid];
    __syncthreads();
    int w = tid >> 5, l = tid & 31;
    #pragma unroll
    for (int i = 0; i < 4; i++) {
        int p = (w << 2) | i;
        int n = s_inv[p];                       // warp-uniform branch
        if (n >= 0) {
            const float* fr = g_feat + (size_t)n * D_MODEL;
            #pragma unroll
            for (int j = 0; j < 4; j++)
                tile[p * 129 + l + 32 * j] = fr[l + 32 * j];
        } else {
            #pragma unroll
            for (int j = 0; j < 4; j++)
                tile[p * 129 + l + 32 * j] = 0.f;
        }
    }
    __syncthreads();
    int b  = base / PLANE;
    int yx = base - b * PLANE;
    float* outp = out + (size_t)b * ((size_t)D_MODEL * PLANE) + yx + l;
    #pragma unroll
    for (int i = 0; i < 16; i++) {
        int c = (w << 4) | i;
        outp[(size_t)c * PLANE] = tile[l * 129 + c];   // bank (l+c)%32: clean
    }
}

extern "C" void kernel_launch(void* const* d_in, const int* in_sizes, int n_in,
                              void* d_out, int out_size) {
    const float* V     = (const float*)d_in[0];
    const float* W0    = (const float*)d_in[1];
    const float* b0    = (const float*)d_in[2];
    const int*   c32   = (const int*)d_in[3];
    float* out = (float*)d_out;

    k_transpose_w<<<64, 256>>>(W0);
    k_init_inv<<<625, 256>>>();
    k_detect<<<1, 32>>>(c32);
    k_scatter<<<(N_VOX + 255) / 256, 256>>>(c32);
    k_gemm<<<N_VOX / BM, 256>>>(V, b0);
    k_gather<<<NPOS / 32, 256>>>(out);
}

// round 4
// speedup vs baseline: 1.6587x; 1.6587x over previous
#include <cuda_runtime.h>
#include <cuda_bf16.h>
#include <cstdint>
#include <cstddef>

#define N_VOX   200000
#define C_IN    128
#define D_MODEL 128
#define NY      400
#define NX      400
#define NB      4
#define PLANE   (NY*NX)        /* 160000 */
#define NPOS    (NB*PLANE)     /* 640000 */

typedef unsigned int u32;

// ---- scratch (device globals; 16B-aligned via vector types) ----
__device__ float4 g_feat4[(size_t)N_VOX * (D_MODEL/4)];   // 102.4 MB
__device__ float4 g_Wh4[2048];   // 32KB: bf16 hi image of W0 [n][k] row-major
__device__ float4 g_Wl4[2048];   // 32KB: bf16 lo image
__device__ int4   g_inv4[NPOS/4];
__device__ int    g_is64;

#define g_feat ((float*)g_feat4)
#define g_inv  ((int*)g_inv4)

// ---- bf16 hi/lo split of 8 floats ----
union BF16x8 { __nv_bfloat16 h[8]; float4 v; };
__device__ __forceinline__ void split8(const float* f, BF16x8& hi, BF16x8& lo) {
    #pragma unroll
    for (int j = 0; j < 8; j++) {
        __nv_bfloat16 h = __float2bfloat16(f[j]);
        hi.h[j] = h;
        lo.h[j] = __float2bfloat16(f[j] - __bfloat162float(h));
    }
}

__device__ __forceinline__ u32 smem_u32(const void* p) {
    u32 a;
    asm("{ .reg .u64 t; cvta.to.shared.u64 t, %1; cvt.u32.u64 %0, t; }"
        : "=r"(a) : "l"(p));
    return a;
}
__device__ __forceinline__ void ldsm_x4(u32 addr, u32& r0, u32& r1, u32& r2, u32& r3) {
    asm volatile("ldmatrix.sync.aligned.m8n8.x4.shared.b16 {%0,%1,%2,%3}, [%4];"
                 : "=r"(r0), "=r"(r1), "=r"(r2), "=r"(r3) : "r"(addr));
}
__device__ __forceinline__ void mma16816(float* c, const u32* a, const u32* b) {
    asm volatile(
        "mma.sync.aligned.m16n8k16.row.col.f32.bf16.bf16.f32 "
        "{%0,%1,%2,%3}, {%4,%5,%6,%7}, {%8,%9}, {%0,%1,%2,%3};"
        : "+f"(c[0]), "+f"(c[1]), "+f"(c[2]), "+f"(c[3])
        : "r"(a[0]), "r"(a[1]), "r"(a[2]), "r"(a[3]), "r"(b[0]), "r"(b[1]));
}

// ---- kernel 1: split W0 into bf16 hi/lo row-major images (one-time) ----
__global__ void k_prep_w(const float* __restrict__ W0) {
    int i = blockIdx.x * 256 + threadIdx.x;   // 2048 groups of 8 elems
    float f[8];
    #pragma unroll
    for (int j = 0; j < 8; j++) f[j] = W0[i * 8 + j];
    BF16x8 hi, lo; split8(f, hi, lo);
    g_Wh4[i] = hi.v;
    g_Wl4[i] = lo.v;
}

// ---- kernel 2: init inverse map ----
__global__ void k_init_inv() {
    int idx = blockIdx.x * 256 + threadIdx.x;   // 160000 int4 exactly (625 blocks)
    g_inv4[idx] = make_int4(-1, -1, -1, -1);
}

// ---- kernel 2b: coors dtype detect (int64 words [b,0,0,0,y,0,x,0]) ----
__global__ void k_detect(const int* __restrict__ c32) {
    int l = threadIdx.x;                         // 32 threads
    int v = c32[8 * l + 3] | c32[8 * l + 7];
    unsigned any = __ballot_sync(0xFFFFFFFF, v != 0);
    if (l == 0) g_is64 = (any == 0) ? 1 : 0;
}

// ---- kernel 3: scatter voxel index into inverse map ----
__global__ void k_scatter(const int* __restrict__ c32) {
    int n = blockIdx.x * 256 + threadIdx.x;
    if (n >= N_VOX) return;
    int b, y, x;
    if (g_is64) { b = c32[8*n + 0]; y = c32[8*n + 4]; x = c32[8*n + 6]; }
    else        { b = c32[4*n + 0]; y = c32[4*n + 2]; x = c32[4*n + 3]; }
    g_inv[b * PLANE + y * NX + x] = n;
}

// ---- kernel 4: mma.sync GEMM  feat = V @ W0^T + b0 (bf16 hi/lo, 3 products)
// CTA: 128x128xK128. 8 warps: wm=w&3 (rows 32wm), wn=w>>2 (cols 64wn).
// smem tiles stride 136 bf16 (272B): ldmatrix banks (4r+c)%32, conflict-free.
#define TSTRIDE 136
#define TILE_ELEMS (128 * TSTRIDE)   /* 17408 bf16 = 34816 B */

__global__ __launch_bounds__(256, 1) void k_gemm(const float* __restrict__ V,
                                                 const float* __restrict__ b0) {
    extern __shared__ __align__(16) __nv_bfloat16 sm[];
    __nv_bfloat16* Ah = sm;
    __nv_bfloat16* Al = sm + TILE_ELEMS;
    __nv_bfloat16* Wh = sm + 2 * TILE_ELEMS;
    __nv_bfloat16* Wl = sm + 3 * TILE_ELEMS;

    int tid = threadIdx.x, w = tid >> 5, lane = tid & 31;
    int row_base = blockIdx.x * 128;

    // stage W hi/lo (64KB from L2-resident pre-split images)
    #pragma unroll
    for (int i = 0; i < 8; i++) {
        int x = tid + 256 * i;                  // 2048 float4 per tile
        int n = x >> 4, j = x & 15;
        *(float4*)(Wh + n * TSTRIDE + 8 * j) = g_Wh4[x];
        *(float4*)(Wl + n * TSTRIDE + 8 * j) = g_Wl4[x];
    }

    // stage A: thread t -> row t>>1, half t&1 (64 cols); split to bf16 hi/lo
    {
        int r = tid >> 1, h = tid & 1;
        int row = row_base + r;
        const float4* src = (const float4*)(V + (size_t)row * 128 + 64 * h);
        #pragma unroll
        for (int j = 0; j < 8; j++) {
            float f[8];
            if (row < N_VOX) {
                float4 a = src[2 * j], b = src[2 * j + 1];
                f[0]=a.x; f[1]=a.y; f[2]=a.z; f[3]=a.w;
                f[4]=b.x; f[5]=b.y; f[6]=b.z; f[7]=b.w;
            } else {
                #pragma unroll
                for (int q = 0; q < 8; q++) f[q] = 0.f;
            }
            BF16x8 hi, lo; split8(f, hi, lo);
            int off = r * TSTRIDE + 64 * h + 8 * j;
            *(float4*)(Ah + off) = hi.v;
            *(float4*)(Al + off) = lo.v;
        }
    }
    __syncthreads();

    int wm = w & 3, wn = w >> 2;
    float acc[2][8][4];
    #pragma unroll
    for (int mt = 0; mt < 2; mt++)
        #pragma unroll
        for (int nt = 0; nt < 8; nt++)
            #pragma unroll
            for (int q = 0; q < 4; q++) acc[mt][nt][q] = 0.f;

    // per-lane ldmatrix row/col offsets
    int a_row = 32 * wm + (lane & 15);          // + 16*mt
    int b_row = 64 * wn + (lane & 15);          // + 16*q
    int c_half = (lane >> 4) << 3;              // k offset 0 or 8
    u32 ah_base = smem_u32(Ah), al_base = smem_u32(Al);
    u32 wh_base = smem_u32(Wh), wl_base = smem_u32(Wl);

    #pragma unroll
    for (int ks = 0; ks < 8; ks++) {
        int kb = 16 * ks + c_half;
        u32 aH[2][4], aL[2][4], bH[8][2], bL[8][2];
        #pragma unroll
        for (int mt = 0; mt < 2; mt++) {
            u32 off = (u32)(((a_row + 16 * mt) * TSTRIDE + kb) * 2);
            ldsm_x4(ah_base + off, aH[mt][0], aH[mt][1], aH[mt][2], aH[mt][3]);
            ldsm_x4(al_base + off, aL[mt][0], aL[mt][1], aL[mt][2], aL[mt][3]);
        }
        #pragma unroll
        for (int q = 0; q < 4; q++) {
            u32 off = (u32)(((b_row + 16 * q) * TSTRIDE + kb) * 2);
            u32 r0, r1, r2, r3;
            ldsm_x4(wh_base + off, r0, r1, r2, r3);
            bH[2*q][0] = r0; bH[2*q+1][0] = r1; bH[2*q][1] = r2; bH[2*q+1][1] = r3;
            ldsm_x4(wl_base + off, r0, r1, r2, r3);
            bL[2*q][0] = r0; bL[2*q+1][0] = r1; bL[2*q][1] = r2; bL[2*q+1][1] = r3;
        }
        #pragma unroll
        for (int mt = 0; mt < 2; mt++)
            #pragma unroll
            for (int nt = 0; nt < 8; nt++) {
                mma16816(acc[mt][nt], aH[mt], bH[nt]);
                mma16816(acc[mt][nt], aH[mt], bL[nt]);
                mma16816(acc[mt][nt], aL[mt], bH[nt]);
            }
    }

    // epilogue: c-fragment float2 stores (4 lanes per 32B sector) + bias
    int cp = 2 * (lane & 3);                    // col pair within n-tile
    float2* feat2 = (float2*)g_feat;
    #pragma unroll
    for (int nt = 0; nt < 8; nt++) {
        int c = 64 * wn + 8 * nt + cp;
        float blo = __ldg(b0 + c), bhi = __ldg(b0 + c + 1);
        #pragma unroll
        for (int mt = 0; mt < 2; mt++) {
            int r0 = row_base + 32 * wm + 16 * mt + (lane >> 2);
            if (r0 < N_VOX)
                feat2[(size_t)r0 * 64 + (c >> 1)] =
                    make_float2(acc[mt][nt][0] + blo, acc[mt][nt][1] + bhi);
            int r1 = r0 + 8;
            if (r1 < N_VOX)
                feat2[(size_t)r1 * 64 + (c >> 1)] =
                    make_float2(acc[mt][nt][2] + blo, acc[mt][nt][3] + bhi);
        }
    }
}

// ---- kernel 5: gather + transpose into [B, C, NY, NX] ----
__global__ __launch_bounds__(256) void k_gather(float* __restrict__ out) {
    __shared__ int   s_inv[32];
    __shared__ float tile[32 * 129];
    int base = blockIdx.x * 32;
    int tid = threadIdx.x;
    if (tid < 32) s_inv[tid] = g_inv[base + tid];
    __syncthreads();
    int w = tid >> 5, l = tid & 31;
    #pragma unroll
    for (int i = 0; i < 4; i++) {
        int p = (w << 2) | i;
        int n = s_inv[p];
        if (n >= 0) {
            const float* fr = g_feat + (size_t)n * D_MODEL;
            #pragma unroll
            for (int j = 0; j < 4; j++)
                tile[p * 129 + l + 32 * j] = fr[l + 32 * j];
        } else {
            #pragma unroll
            for (int j = 0; j < 4; j++)
                tile[p * 129 + l + 32 * j] = 0.f;
        }
    }
    __syncthreads();
    int b  = base / PLANE;
    int yx = base - b * PLANE;
    float* outp = out + (size_t)b * ((size_t)D_MODEL * PLANE) + yx + l;
    #pragma unroll
    for (int i = 0; i < 16; i++) {
        int c = (w << 4) | i;
        outp[(size_t)c * PLANE] = tile[l * 129 + c];
    }
}

extern "C" void kernel_launch(void* const* d_in, const int* in_sizes, int n_in,
                              void* d_out, int out_size) {
    const float* V   = (const float*)d_in[0];
    const float* W0  = (const float*)d_in[1];
    const float* b0  = (const float*)d_in[2];
    const int*   c32 = (const int*)d_in[3];
    float* out = (float*)d_out;

    cudaFuncSetAttribute((const void*)k_gemm,
                         cudaFuncAttributeMaxDynamicSharedMemorySize,
                         4 * TILE_ELEMS * 2);

    k_prep_w<<<8, 256>>>(W0);
    k_init_inv<<<625, 256>>>();
    k_detect<<<1, 32>>>(c32);
    k_scatter<<<(N_VOX + 255) / 256, 256>>>(c32);
    k_gemm<<<(N_VOX + 127) / 128, 256, 4 * TILE_ELEMS * 2>>>(V, b0);
    k_gather<<<NPOS / 32, 256>>>(out);
}

// round 5
// speedup vs baseline: 1.9903x; 1.1999x over previous
#include <cuda_runtime.h>
#include <cuda_bf16.h>
#include <cstdint>
#include <cstddef>

#define N_VOX   200000
#define C_IN    128
#define D_MODEL 128
#define NY      400
#define NX      400
#define NB      4
#define PLANE   (NY*NX)        /* 160000 */
#define NPOS    (NB*PLANE)     /* 640000 */

typedef unsigned int u32;

// ---- scratch (device globals; 16B-aligned via vector types) ----
__device__ float4 g_feat4[(size_t)N_VOX * (D_MODEL/4)];   // 102.4 MB
__device__ float4 g_Wh4[2048];   // 32KB: bf16 hi image of W0 [n][k] row-major
__device__ float4 g_Wl4[2048];   // 32KB: bf16 lo image
__device__ int4   g_inv4[NPOS/4];

#define g_feat ((float*)g_feat4)
#define g_inv  ((int*)g_inv4)

// ---- bf16 hi/lo split of 8 floats ----
union BF16x8 { __nv_bfloat16 h[8]; float4 v; };
__device__ __forceinline__ void split8(const float* f, BF16x8& hi, BF16x8& lo) {
    #pragma unroll
    for (int j = 0; j < 8; j++) {
        __nv_bfloat16 h = __float2bfloat16(f[j]);
        hi.h[j] = h;
        lo.h[j] = __float2bfloat16(f[j] - __bfloat162float(h));
    }
}

__device__ __forceinline__ u32 smem_u32(const void* p) {
    u32 a;
    asm("{ .reg .u64 t; cvta.to.shared.u64 t, %1; cvt.u32.u64 %0, t; }"
        : "=r"(a) : "l"(p));
    return a;
}
__device__ __forceinline__ void ldsm_x4(u32 addr, u32& r0, u32& r1, u32& r2, u32& r3) {
    asm volatile("ldmatrix.sync.aligned.m8n8.x4.shared.b16 {%0,%1,%2,%3}, [%4];"
                 : "=r"(r0), "=r"(r1), "=r"(r2), "=r"(r3) : "r"(addr));
}
__device__ __forceinline__ void mma16816(float* c, const u32* a, const u32* b) {
    asm volatile(
        "mma.sync.aligned.m16n8k16.row.col.f32.bf16.bf16.f32 "
        "{%0,%1,%2,%3}, {%4,%5,%6,%7}, {%8,%9}, {%0,%1,%2,%3};"
        : "+f"(c[0]), "+f"(c[1]), "+f"(c[2]), "+f"(c[3])
        : "r"(a[0]), "r"(a[1]), "r"(a[2]), "r"(a[3]), "r"(b[0]), "r"(b[1]));
}

// ---- kernel 1: setup = init_inv (blocks 0..624) + prep_w (blocks 625..632) ----
__global__ void k_setup(const float* __restrict__ W0) {
    int b = blockIdx.x, t = threadIdx.x;
    if (b < 625) {
        g_inv4[b * 256 + t] = make_int4(-1, -1, -1, -1);   // 160000 int4 exactly
    } else {
        int i = (b - 625) * 256 + t;   // 2048 groups of 8 elems
        float f[8];
        #pragma unroll
        for (int j = 0; j < 8; j++) f[j] = W0[i * 8 + j];
        BF16x8 hi, lo; split8(f, hi, lo);
        g_Wh4[i] = hi.v;
        g_Wl4[i] = lo.v;
    }
}

// ---- kernel 2: scatter with inline per-warp dtype detection ----
// int64 coors as 32-bit words: [b,0, 0,0, y,0, x,0] -> odd words all zero.
// Detection samples the first 32 entries (256 ints: in-bounds for both dtypes).
__global__ void k_scatter(const int* __restrict__ c32) {
    int l = threadIdx.x & 31;
    int v = c32[8 * l + 3] | c32[8 * l + 7];
    unsigned any = __ballot_sync(0xFFFFFFFF, v != 0);
    bool is64 = (any == 0);
    int n = blockIdx.x * 256 + threadIdx.x;
    if (n >= N_VOX) return;
    int b, y, x;
    if (is64) { b = c32[8*n + 0]; y = c32[8*n + 4]; x = c32[8*n + 6]; }
    else      { b = c32[4*n + 0]; y = c32[4*n + 2]; x = c32[4*n + 3]; }
    g_inv[b * PLANE + y * NX + x] = n;
}

// ---- kernel 3: mma.sync GEMM  feat = V @ W0^T + b0 (bf16 hi/lo, 3 products)
// BM=64 for 2 CTAs/SM (load/compute overlap across CTAs).
// 8 warps as 2m x 4n: warp -> 32 rows x 32 cols. K=128 resident.
// smem tiles stride 136 bf16 (272B): ldmatrix banks (4r+c)%32, conflict-free.
#define TSTRIDE 136
#define A_ELEMS (64 * TSTRIDE)    /* 8704 bf16 = 17408 B */
#define W_ELEMS (128 * TSTRIDE)   /* 17408 bf16 = 34816 B */
#define GEMM_SMEM ((2 * A_ELEMS + 2 * W_ELEMS) * 2)   /* 104448 B */

__global__ __launch_bounds__(256, 2) void k_gemm(const float* __restrict__ V,
                                                 const float* __restrict__ b0) {
    extern __shared__ __align__(16) __nv_bfloat16 sm[];
    __nv_bfloat16* Ah = sm;
    __nv_bfloat16* Al = sm + A_ELEMS;
    __nv_bfloat16* Wh = sm + 2 * A_ELEMS;
    __nv_bfloat16* Wl = sm + 2 * A_ELEMS + W_ELEMS;

    int tid = threadIdx.x, w = tid >> 5, lane = tid & 31;
    int row_base = blockIdx.x * 64;             // 200000 = 64*3125 exact

    // stage W hi/lo (64KB, L2-resident pre-split images)
    #pragma unroll
    for (int i = 0; i < 8; i++) {
        int x = tid + 256 * i;                  // 2048 float4 per tile
        int n = x >> 4, j = x & 15;
        *(float4*)(Wh + n * TSTRIDE + 8 * j) = g_Wh4[x];
        *(float4*)(Wl + n * TSTRIDE + 8 * j) = g_Wl4[x];
    }

    // stage A: 1024 groups of 8 floats; evict-first loads (read-once stream)
    #pragma unroll
    for (int i = 0; i < 4; i++) {
        int x = tid + 256 * i;
        int r = x >> 4, j = x & 15;             // r: 0..63, cols 8j..8j+7
        const float4* src = (const float4*)(V + (size_t)(row_base + r) * 128 + 8 * j);
        float4 a = __ldcs(src), b = __ldcs(src + 1);
        float f[8] = {a.x, a.y, a.z, a.w, b.x, b.y, b.z, b.w};
        BF16x8 hi, lo; split8(f, hi, lo);
        int off = r * TSTRIDE + 8 * j;
        *(float4*)(Ah + off) = hi.v;
        *(float4*)(Al + off) = lo.v;
    }
    __syncthreads();

    int wm = w & 1, wn = w >> 1;                // 2m x 4n warp grid
    float acc[2][4][4];
    #pragma unroll
    for (int mt = 0; mt < 2; mt++)
        #pragma unroll
        for (int nt = 0; nt < 4; nt++)
            #pragma unroll
            for (int q = 0; q < 4; q++) acc[mt][nt][q] = 0.f;

    int a_row = 32 * wm + (lane & 15);          // + 16*mt
    int b_row = 32 * wn + (lane & 15);          // + 16*q
    int c_half = (lane >> 4) << 3;              // k offset 0 or 8
    u32 ah_base = smem_u32(Ah), al_base = smem_u32(Al);
    u32 wh_base = smem_u32(Wh), wl_base = smem_u32(Wl);

    #pragma unroll
    for (int ks = 0; ks < 8; ks++) {
        int kb = 16 * ks + c_half;
        u32 aH[2][4], aL[2][4], bH[4][2], bL[4][2];
        #pragma unroll
        for (int mt = 0; mt < 2; mt++) {
            u32 off = (u32)(((a_row + 16 * mt) * TSTRIDE + kb) * 2);
            ldsm_x4(ah_base + off, aH[mt][0], aH[mt][1], aH[mt][2], aH[mt][3]);
            ldsm_x4(al_base + off, aL[mt][0], aL[mt][1], aL[mt][2], aL[mt][3]);
        }
        #pragma unroll
        for (int q = 0; q < 2; q++) {
            u32 off = (u32)(((b_row + 16 * q) * TSTRIDE + kb) * 2);
            u32 r0, r1, r2, r3;
            ldsm_x4(wh_base + off, r0, r1, r2, r3);
            bH[2*q][0] = r0; bH[2*q+1][0] = r1; bH[2*q][1] = r2; bH[2*q+1][1] = r3;
            ldsm_x4(wl_base + off, r0, r1, r2, r3);
            bL[2*q][0] = r0; bL[2*q+1][0] = r1; bL[2*q][1] = r2; bL[2*q+1][1] = r3;
        }
        #pragma unroll
        for (int mt = 0; mt < 2; mt++)
            #pragma unroll
            for (int nt = 0; nt < 4; nt++) {
                mma16816(acc[mt][nt], aH[mt], bH[nt]);
                mma16816(acc[mt][nt], aH[mt], bL[nt]);
                mma16816(acc[mt][nt], aL[mt], bH[nt]);
            }
    }

    // epilogue: c-fragment float2 stores + bias (writes allocate in L2)
    int cp = 2 * (lane & 3);
    float2* feat2 = (float2*)g_feat;
    #pragma unroll
    for (int nt = 0; nt < 4; nt++) {
        int c = 32 * wn + 8 * nt + cp;
        float blo = __ldg(b0 + c), bhi = __ldg(b0 + c + 1);
        #pragma unroll
        for (int mt = 0; mt < 2; mt++) {
            int r0 = row_base + 32 * wm + 16 * mt + (lane >> 2);
            feat2[(size_t)r0 * 64 + (c >> 1)] =
                make_float2(acc[mt][nt][0] + blo, acc[mt][nt][1] + bhi);
            feat2[(size_t)(r0 + 8) * 64 + (c >> 1)] =
                make_float2(acc[mt][nt][2] + blo, acc[mt][nt][3] + bhi);
        }
    }
}

// ---- kernel 4: gather + transpose into [B, C, NY, NX] ----
// feat reads should hit L2 (feat ~102MB vs 126MB L2, written just before);
// out writes use streaming .cs so they do not evict feat.
__global__ __launch_bounds__(256) void k_gather(float* __restrict__ out) {
    __shared__ int   s_inv[32];
    __shared__ float tile[32 * 129];
    int base = blockIdx.x * 32;
    int tid = threadIdx.x;
    if (tid < 32) s_inv[tid] = g_inv[base + tid];
    __syncthreads();
    int w = tid >> 5, l = tid & 31;
    #pragma unroll
    for (int i = 0; i < 4; i++) {
        int p = (w << 2) | i;
        int n = s_inv[p];
        if (n >= 0) {
            const float* fr = g_feat + (size_t)n * D_MODEL;
            #pragma unroll
            for (int j = 0; j < 4; j++)
                tile[p * 129 + l + 32 * j] = fr[l + 32 * j];
        } else {
            #pragma unroll
            for (int j = 0; j < 4; j++)
                tile[p * 129 + l + 32 * j] = 0.f;
        }
    }
    __syncthreads();
    int b  = base / PLANE;
    int yx = base - b * PLANE;
    float* outp = out + (size_t)b * ((size_t)D_MODEL * PLANE) + yx + l;
    #pragma unroll
    for (int i = 0; i < 16; i++) {
        int c = (w << 4) | i;
        __stcs(outp + (size_t)c * PLANE, tile[l * 129 + c]);
    }
}

extern "C" void kernel_launch(void* const* d_in, const int* in_sizes, int n_in,
                              void* d_out, int out_size) {
    const float* V   = (const float*)d_in[0];
    const float* W0  = (const float*)d_in[1];
    const float* b0  = (const float*)d_in[2];
    const int*   c32 = (const int*)d_in[3];
    float* out = (float*)d_out;

    cudaFuncSetAttribute((const void*)k_gemm,
                         cudaFuncAttributeMaxDynamicSharedMemorySize, GEMM_SMEM);

    k_setup<<<633, 256>>>(W0);
    k_scatter<<<(N_VOX + 255) / 256, 256>>>(c32);
    k_gemm<<<N_VOX / 64, 256, GEMM_SMEM>>>(V, b0);
    k_gather<<<NPOS / 32, 256>>>(out);
}

// round 6
// speedup vs baseline: 2.0576x; 1.0338x over previous
#include <cuda_runtime.h>
#include <cuda_bf16.h>
#include <cstdint>
#include <cstddef>

#define N_VOX   200000
#define C_IN    128
#define D_MODEL 128
#define NY      400
#define NX      400
#define NB      4
#define PLANE   (NY*NX)        /* 160000 */
#define NPOS    (NB*PLANE)     /* 640000 */

typedef unsigned int u32;

// ---- scratch (device globals; 16B-aligned via vector types) ----
__device__ float4 g_feat4[(size_t)N_VOX * (D_MODEL/4)];   // 102.4 MB
__device__ uint4  g_Wh4[2048];   // 32KB: bf16 hi image of W0 [n][k] row-major
__device__ uint4  g_Wl4[2048];   // 32KB: bf16 lo image
__device__ int4   g_inv4[NPOS/4];

#define g_feat ((float*)g_feat4)
#define g_inv  ((int*)g_inv4)

// ---- packed bf16 hi/lo split: 2 floats -> hi word + lo word ----
__device__ __forceinline__ u32 bf2(float fhi, float flo) {
    u32 w; asm("cvt.rn.bf16x2.f32 %0, %1, %2;" : "=r"(w) : "f"(fhi), "f"(flo));
    return w;
}
__device__ __forceinline__ void split2(float f0, float f1, u32& hw, u32& lw) {
    hw = bf2(f1, f0);                               // lo half = f0
    float h0 = __uint_as_float(hw << 16);           // bf16->f32 = shift (ALU)
    float h1 = __uint_as_float(hw & 0xFFFF0000u);
    lw = bf2(f1 - h1, f0 - h0);
}
// 8 floats (two float4) -> hi uint4 + lo uint4 (8 consecutive bf16 each)
__device__ __forceinline__ void split8p(float4 a, float4 b, uint4& hi, uint4& lo) {
    split2(a.x, a.y, hi.x, lo.x);
    split2(a.z, a.w, hi.y, lo.y);
    split2(b.x, b.y, hi.z, lo.z);
    split2(b.z, b.w, hi.w, lo.w);
}

__device__ __forceinline__ u32 smem_u32(const void* p) {
    u32 a;
    asm("{ .reg .u64 t; cvta.to.shared.u64 t, %1; cvt.u32.u64 %0, t; }"
        : "=r"(a) : "l"(p));
    return a;
}
__device__ __forceinline__ void ldsm_x4(u32 addr, u32& r0, u32& r1, u32& r2, u32& r3) {
    asm volatile("ldmatrix.sync.aligned.m8n8.x4.shared.b16 {%0,%1,%2,%3}, [%4];"
                 : "=r"(r0), "=r"(r1), "=r"(r2), "=r"(r3) : "r"(addr));
}
__device__ __forceinline__ void mma16816(float* c, const u32* a, const u32* b) {
    asm volatile(
        "mma.sync.aligned.m16n8k16.row.col.f32.bf16.bf16.f32 "
        "{%0,%1,%2,%3}, {%4,%5,%6,%7}, {%8,%9}, {%0,%1,%2,%3};"
        : "+f"(c[0]), "+f"(c[1]), "+f"(c[2]), "+f"(c[3])
        : "r"(a[0]), "r"(a[1]), "r"(a[2]), "r"(a[3]), "r"(b[0]), "r"(b[1]));
}

// ---- kernel 1: setup = init_inv (blocks 0..624) + prep_w (blocks 625..632) ----
__global__ void k_setup(const float* __restrict__ W0) {
    int b = blockIdx.x, t = threadIdx.x;
    if (b < 625) {
        g_inv4[b * 256 + t] = make_int4(-1, -1, -1, -1);   // 160000 int4 exactly
    } else {
        int i = (b - 625) * 256 + t;   // 2048 groups of 8 elems
        const float4* src = (const float4*)(W0 + i * 8);
        uint4 hi, lo; split8p(src[0], src[1], hi, lo);
        g_Wh4[i] = hi;
        g_Wl4[i] = lo;
    }
}

// ---- kernel 2: scatter with inline per-warp dtype detection ----
// int64 coors as 32-bit words: [b,0, 0,0, y,0, x,0] -> odd words all zero.
__global__ void k_scatter(const int* __restrict__ c32) {
    int l = threadIdx.x & 31;
    int v = c32[8 * l + 3] | c32[8 * l + 7];
    unsigned any = __ballot_sync(0xFFFFFFFF, v != 0);
    bool is64 = (any == 0);
    int n = blockIdx.x * 256 + threadIdx.x;
    if (n >= N_VOX) return;
    int b, y, x;
    if (is64) { b = c32[8*n + 0]; y = c32[8*n + 4]; x = c32[8*n + 6]; }
    else      { b = c32[4*n + 0]; y = c32[4*n + 2]; x = c32[4*n + 3]; }
    g_inv[b * PLANE + y * NX + x] = n;
}

// ---- kernel 3: mma.sync GEMM  feat = V @ W0^T + b0 (bf16 hi/lo, 3 products)
// BM=64, 2 CTAs/SM. 8 warps as 2m x 4n (warp = 32 rows x 32 cols). K=128.
// smem tiles stride 136 bf16 (272B): ldmatrix banks (4r+c)%32, conflict-free.
#define TSTRIDE 136
#define A_ELEMS (64 * TSTRIDE)    /* 8704 bf16 = 17408 B */
#define W_ELEMS (128 * TSTRIDE)   /* 17408 bf16 = 34816 B */
#define GEMM_SMEM ((2 * A_ELEMS + 2 * W_ELEMS) * 2)   /* 104448 B */

__global__ __launch_bounds__(256, 2) void k_gemm(const float* __restrict__ V,
                                                 const float* __restrict__ b0) {
    extern __shared__ __align__(16) __nv_bfloat16 sm[];
    __nv_bfloat16* Ah = sm;
    __nv_bfloat16* Al = sm + A_ELEMS;
    __nv_bfloat16* Wh = sm + 2 * A_ELEMS;
    __nv_bfloat16* Wl = sm + 2 * A_ELEMS + W_ELEMS;

    int tid = threadIdx.x, w = tid >> 5, lane = tid & 31;
    int row_base = blockIdx.x * 64;             // 200000 = 64*3125 exact

    // stage W hi/lo (64KB, L2-resident pre-split images)
    #pragma unroll
    for (int i = 0; i < 8; i++) {
        int x = tid + 256 * i;                  // 2048 uint4 per tile
        int n = x >> 4, j = x & 15;
        *(uint4*)(Wh + n * TSTRIDE + 8 * j) = g_Wh4[x];
        *(uint4*)(Wl + n * TSTRIDE + 8 * j) = g_Wl4[x];
    }

    // stage A: 1024 groups of 8 floats; packed split; evict-first loads
    #pragma unroll
    for (int i = 0; i < 4; i++) {
        int x = tid + 256 * i;
        int r = x >> 4, j = x & 15;             // r: 0..63, cols 8j..8j+7
        const float4* src = (const float4*)(V + (size_t)(row_base + r) * 128 + 8 * j);
        float4 a = __ldcs(src), b = __ldcs(src + 1);
        uint4 hi, lo; split8p(a, b, hi, lo);
        int off = r * TSTRIDE + 8 * j;
        *(uint4*)(Ah + off) = hi;
        *(uint4*)(Al + off) = lo;
    }
    __syncthreads();

    int wm = w & 1, wn = w >> 1;                // 2m x 4n warp grid
    float acc[2][4][4];
    #pragma unroll
    for (int mt = 0; mt < 2; mt++)
        #pragma unroll
        for (int nt = 0; nt < 4; nt++)
            #pragma unroll
            for (int q = 0; q < 4; q++) acc[mt][nt][q] = 0.f;

    int a_row = 32 * wm + (lane & 15);          // + 16*mt
    int b_row = 32 * wn + (lane & 15);          // + 16*q
    int c_half = (lane >> 4) << 3;              // k offset 0 or 8
    u32 ah_base = smem_u32(Ah), al_base = smem_u32(Al);
    u32 wh_base = smem_u32(Wh), wl_base = smem_u32(Wl);

    #pragma unroll
    for (int ks = 0; ks < 8; ks++) {
        int kb = 16 * ks + c_half;
        u32 aH[2][4], aL[2][4], bH[4][2], bL[4][2];
        #pragma unroll
        for (int mt = 0; mt < 2; mt++) {
            u32 off = (u32)(((a_row + 16 * mt) * TSTRIDE + kb) * 2);
            ldsm_x4(ah_base + off, aH[mt][0], aH[mt][1], aH[mt][2], aH[mt][3]);
            ldsm_x4(al_base + off, aL[mt][0], aL[mt][1], aL[mt][2], aL[mt][3]);
        }
        #pragma unroll
        for (int q = 0; q < 2; q++) {
            u32 off = (u32)(((b_row + 16 * q) * TSTRIDE + kb) * 2);
            u32 r0, r1, r2, r3;
            ldsm_x4(wh_base + off, r0, r1, r2, r3);
            bH[2*q][0] = r0; bH[2*q+1][0] = r1; bH[2*q][1] = r2; bH[2*q+1][1] = r3;
            ldsm_x4(wl_base + off, r0, r1, r2, r3);
            bL[2*q][0] = r0; bL[2*q+1][0] = r1; bL[2*q][1] = r2; bL[2*q+1][1] = r3;
        }
        #pragma unroll
        for (int mt = 0; mt < 2; mt++)
            #pragma unroll
            for (int nt = 0; nt < 4; nt++) {
                mma16816(acc[mt][nt], aH[mt], bH[nt]);
                mma16816(acc[mt][nt], aH[mt], bL[nt]);
                mma16816(acc[mt][nt], aL[mt], bH[nt]);
            }
    }

    // epilogue: c-fragment float2 stores + bias (writes allocate in L2)
    int cp = 2 * (lane & 3);
    float2* feat2 = (float2*)g_feat;
    #pragma unroll
    for (int nt = 0; nt < 4; nt++) {
        int c = 32 * wn + 8 * nt + cp;
        float blo = __ldg(b0 + c), bhi = __ldg(b0 + c + 1);
        #pragma unroll
        for (int mt = 0; mt < 2; mt++) {
            int r0 = row_base + 32 * wm + 16 * mt + (lane >> 2);
            feat2[(size_t)r0 * 64 + (c >> 1)] =
                make_float2(acc[mt][nt][0] + blo, acc[mt][nt][1] + bhi);
            feat2[(size_t)(r0 + 8) * 64 + (c >> 1)] =
                make_float2(acc[mt][nt][2] + blo, acc[mt][nt][3] + bhi);
        }
    }
}

// ---- kernel 4: gather + transpose into [B, C, NY, NX] ----
// At HBM write floor (~3.8 TB/s for the 327MB output) -- keep structure.
__global__ __launch_bounds__(256) void k_gather(float* __restrict__ out) {
    __shared__ int   s_inv[32];
    __shared__ float tile[32 * 129];
    int base = blockIdx.x * 32;
    int tid = threadIdx.x;
    if (tid < 32) s_inv[tid] = g_inv[base + tid];
    __syncthreads();
    int w = tid >> 5, l = tid & 31;
    #pragma unroll
    for (int i = 0; i < 4; i++) {
        int p = (w << 2) | i;
        int n = s_inv[p];
        if (n >= 0) {
            const float* fr = g_feat + (size_t)n * D_MODEL;
            #pragma unroll
            for (int j = 0; j < 4; j++)
                tile[p * 129 + l + 32 * j] = fr[l + 32 * j];
        } else {
            #pragma unroll
            for (int j = 0; j < 4; j++)
                tile[p * 129 + l + 32 * j] = 0.f;
        }
    }
    __syncthreads();
    int b  = base / PLANE;
    int yx = base - b * PLANE;
    float* outp = out + (size_t)b * ((size_t)D_MODEL * PLANE) + yx + l;
    #pragma unroll
    for (int i = 0; i < 16; i++) {
        int c = (w << 4) | i;
        __stcs(outp + (size_t)c * PLANE, tile[l * 129 + c]);
    }
}

extern "C" void kernel_launch(void* const* d_in, const int* in_sizes, int n_in,
                              void* d_out, int out_size) {
    const float* V   = (const float*)d_in[0];
    const float* W0  = (const float*)d_in[1];
    const float* b0  = (const float*)d_in[2];
    const int*   c32 = (const int*)d_in[3];
    float* out = (float*)d_out;

    cudaFuncSetAttribute((const void*)k_gemm,
                         cudaFuncAttributeMaxDynamicSharedMemorySize, GEMM_SMEM);

    k_setup<<<633, 256>>>(W0);
    k_scatter<<<(N_VOX + 255) / 256, 256>>>(c32);
    k_gemm<<<N_VOX / 64, 256, GEMM_SMEM>>>(V, b0);
    k_gather<<<NPOS / 32, 256>>>(out);
}

// round 8
// speedup vs baseline: 2.3138x; 1.1245x over previous
#include <cuda_runtime.h>
#include <cuda_fp16.h>
#include <cstdint>
#include <cstddef>

#define N_VOX   200000
#define C_IN    128
#define D_MODEL 128
#define NY      400
#define NX      400
#define NB      4
#define PLANE   (NY*NX)        /* 160000 */
#define NPOS    (NB*PLANE)     /* 640000 */

typedef unsigned int u32;

// ---- scratch (device globals; 16B-aligned via vector types) ----
__device__ float4 g_feat4[(size_t)N_VOX * (D_MODEL/4)];   // 102.4 MB
__device__ uint4  g_Wh4[2048];   // 32KB: fp16 image of W0 [n][k] row-major
__device__ int4   g_inv4[NPOS/4];

#define g_feat ((float*)g_feat4)
#define g_inv  ((int*)g_inv4)

// ---- fp16 hi/lo split: 2 floats -> hi half2 word + lo half2 word ----
__device__ __forceinline__ void split2h(float f0, float f1, u32& hw, u32& lw) {
    __half2 h = __float22half2_rn(make_float2(f0, f1));
    hw = *(u32*)&h;
    float2 hf = __half22float2(h);
    __half2 l = __float22half2_rn(make_float2(f0 - hf.x, f1 - hf.y));
    lw = *(u32*)&l;
}
__device__ __forceinline__ void split8h(float4 a, float4 b, uint4& hi, uint4& lo) {
    split2h(a.x, a.y, hi.x, lo.x);
    split2h(a.z, a.w, hi.y, lo.y);
    split2h(b.x, b.y, hi.z, lo.z);
    split2h(b.z, b.w, hi.w, lo.w);
}
__device__ __forceinline__ uint4 round8h(float4 a, float4 b) {
    uint4 hi;
    __half2 h0 = __float22half2_rn(make_float2(a.x, a.y));
    __half2 h1 = __float22half2_rn(make_float2(a.z, a.w));
    __half2 h2 = __float22half2_rn(make_float2(b.x, b.y));
    __half2 h3 = __float22half2_rn(make_float2(b.z, b.w));
    hi.x = *(u32*)&h0; hi.y = *(u32*)&h1; hi.z = *(u32*)&h2; hi.w = *(u32*)&h3;
    return hi;
}

__device__ __forceinline__ u32 smem_u32(const void* p) {
    u32 a;
    asm("{ .reg .u64 t; cvta.to.shared.u64 t, %1; cvt.u32.u64 %0, t; }"
        : "=r"(a) : "l"(p));
    return a;
}
__device__ __forceinline__ void ldsm_x4(u32 addr, u32& r0, u32& r1, u32& r2, u32& r3) {
    asm volatile("ldmatrix.sync.aligned.m8n8.x4.shared.b16 {%0,%1,%2,%3}, [%4];"
                 : "=r"(r0), "=r"(r1), "=r"(r2), "=r"(r3) : "r"(addr));
}
__device__ __forceinline__ void mma16816h(float* c, const u32* a, const u32* b) {
    asm volatile(
        "mma.sync.aligned.m16n8k16.row.col.f32.f16.f16.f32 "
        "{%0,%1,%2,%3}, {%4,%5,%6,%7}, {%8,%9}, {%0,%1,%2,%3};"
        : "+f"(c[0]), "+f"(c[1]), "+f"(c[2]), "+f"(c[3])
        : "r"(a[0]), "r"(a[1]), "r"(a[2]), "r"(a[3]), "r"(b[0]), "r"(b[1]));
}

// ---- kernel 1: setup = init_inv (blocks 0..624) + prep_w (blocks 625..632) ----
__global__ void k_setup(const float* __restrict__ W0) {
    int b = blockIdx.x, t = threadIdx.x;
    if (b < 625) {
        g_inv4[b * 256 + t] = make_int4(-1, -1, -1, -1);   // 160000 int4 exactly
    } else {
        int i = (b - 625) * 256 + t;   // 2048 groups of 8 elems
        const float4* src = (const float4*)(W0 + i * 8);
        g_Wh4[i] = round8h(src[0], src[1]);
    }
}

// ---- kernel 2: scatter with inline per-warp dtype detection ----
// int64 coors as 32-bit words: [b,0, 0,0, y,0, x,0] -> odd words all zero.
__global__ void k_scatter(const int* __restrict__ c32) {
    int l = threadIdx.x & 31;
    int v = c32[8 * l + 3] | c32[8 * l + 7];
    unsigned any = __ballot_sync(0xFFFFFFFF, v != 0);
    bool is64 = (any == 0);
    int n = blockIdx.x * 256 + threadIdx.x;
    if (n >= N_VOX) return;
    int b, y, x;
    if (is64) { b = c32[8*n + 0]; y = c32[8*n + 4]; x = c32[8*n + 6]; }
    else      { b = c32[4*n + 0]; y = c32[4*n + 2]; x = c32[4*n + 3]; }
    g_inv[b * PLANE + y * NX + x] = n;
}

// ---- kernel 3: mma.sync GEMM  feat = V @ W0^T + b0 (fp16 2-product)
// D = (Ah + Al) * Wh, A split into fp16 hi/lo, W rounded to fp16.
// BM=64, 3 CTAs/SM (69.6KB smem each). 8 warps as 2m x 4n. K=128 resident.
// smem tiles stride 136 h16 (272B): ldmatrix banks (4r+c)%32, conflict-free.
#define TSTRIDE 136
#define A_ELEMS (64 * TSTRIDE)    /* 8704 h16 = 17408 B */
#define W_ELEMS (128 * TSTRIDE)   /* 17408 h16 = 34816 B */
#define GEMM_SMEM ((2 * A_ELEMS + W_ELEMS) * 2)   /* 69632 B */

__global__ __launch_bounds__(256, 3) void k_gemm(const float* __restrict__ V,
                                                 const float* __restrict__ b0) {
    extern __shared__ __align__(16) __half sm[];
    __half* Ah = sm;
    __half* Al = sm + A_ELEMS;
    __half* Wh = sm + 2 * A_ELEMS;

    int tid = threadIdx.x, w = tid >> 5, lane = tid & 31;
    int row_base = blockIdx.x * 64;             // 200000 = 64*3125 exact

    // stage W (32KB fp16, L2-resident pre-rounded image)
    #pragma unroll
    for (int i = 0; i < 8; i++) {
        int x = tid + 256 * i;                  // 2048 uint4
        int n = x >> 4, j = x & 15;
        *(uint4*)(Wh + n * TSTRIDE + 8 * j) = g_Wh4[x];
    }

    // stage A: 1024 groups of 8 floats; fp16 hi/lo split; evict-first loads
    #pragma unroll
    for (int i = 0; i < 4; i++) {
        int x = tid + 256 * i;
        int r = x >> 4, j = x & 15;             // r: 0..63, cols 8j..8j+7
        const float4* src = (const float4*)(V + (size_t)(row_base + r) * 128 + 8 * j);
        float4 a = __ldcs(src), b = __ldcs(src + 1);
        uint4 hi, lo; split8h(a, b, hi, lo);
        int off = r * TSTRIDE + 8 * j;
        *(uint4*)(Ah + off) = hi;
        *(uint4*)(Al + off) = lo;
    }
    __syncthreads();

    int wm = w & 1, wn = w >> 1;                // 2m x 4n warp grid
    float acc[2][4][4];
    #pragma unroll
    for (int mt = 0; mt < 2; mt++)
        #pragma unroll
        for (int nt = 0; nt < 4; nt++)
            #pragma unroll
            for (int q = 0; q < 4; q++) acc[mt][nt][q] = 0.f;

    int a_row = 32 * wm + (lane & 15);          // + 16*mt
    int b_row = 32 * wn + (lane & 15);          // + 16*q
    int c_half = (lane >> 4) << 3;              // k offset 0 or 8
    u32 ah_base = smem_u32(Ah), al_base = smem_u32(Al);
    u32 wh_base = smem_u32(Wh);

    #pragma unroll
    for (int ks = 0; ks < 8; ks++) {
        int kb = 16 * ks + c_half;
        u32 aH[2][4], aL[2][4], bH[4][2];
        #pragma unroll
        for (int mt = 0; mt < 2; mt++) {
            u32 off = (u32)(((a_row + 16 * mt) * TSTRIDE + kb) * 2);
            ldsm_x4(ah_base + off, aH[mt][0], aH[mt][1], aH[mt][2], aH[mt][3]);
            ldsm_x4(al_base + off, aL[mt][0], aL[mt][1], aL[mt][2], aL[mt][3]);
        }
        #pragma unroll
        for (int q = 0; q < 2; q++) {
            u32 off = (u32)(((b_row + 16 * q) * TSTRIDE + kb) * 2);
            u32 r0, r1, r2, r3;
            ldsm_x4(wh_base + off, r0, r1, r2, r3);
            bH[2*q][0] = r0; bH[2*q+1][0] = r1; bH[2*q][1] = r2; bH[2*q+1][1] = r3;
        }
        #pragma unroll
        for (int mt = 0; mt < 2; mt++)
            #pragma unroll
            for (int nt = 0; nt < 4; nt++) {
                mma16816h(acc[mt][nt], aH[mt], bH[nt]);
                mma16816h(acc[mt][nt], aL[mt], bH[nt]);
            }
    }

    // epilogue: c-fragment float2 stores + bias (writes allocate in L2)
    int cp = 2 * (lane & 3);
    float2* feat2 = (float2*)g_feat;
    #pragma unroll
    for (int nt = 0; nt < 4; nt++) {
        int c = 32 * wn + 8 * nt + cp;
        float blo = __ldg(b0 + c), bhi = __ldg(b0 + c + 1);
        #pragma unroll
        for (int mt = 0; mt < 2; mt++) {
            int r0 = row_base + 32 * wm + 16 * mt + (lane >> 2);
            feat2[(size_t)r0 * 64 + (c >> 1)] =
                make_float2(acc[mt][nt][0] + blo, acc[mt][nt][1] + bhi);
            feat2[(size_t)(r0 + 8) * 64 + (c >> 1)] =
                make_float2(acc[mt][nt][2] + blo, acc[mt][nt][3] + bhi);
        }
    }
}

// ---- kernel 4: gather + transpose into [B, C, NY, NX] ----
// Proven round-5 version: 32 consecutive positions per block, stride-129
// tile (conflict-free both phases), 128B coalesced cacheline stores.
__global__ __launch_bounds__(256) void k_gather(float* __restrict__ out) {
    __shared__ int   s_inv[32];
    __shared__ float tile[32 * 129];
    int base = blockIdx.x * 32;
    int tid = threadIdx.x;
    if (tid < 32) s_inv[tid] = g_inv[base + tid];
    __syncthreads();
    int w = tid >> 5, l = tid & 31;
    #pragma unroll
    for (int i = 0; i < 4; i++) {
        int p = (w << 2) | i;
        int n = s_inv[p];                       // warp-uniform branch
        if (n >= 0) {
            const float* fr = g_feat + (size_t)n * D_MODEL;
            #pragma unroll
            for (int j = 0; j < 4; j++)
                tile[p * 129 + l + 32 * j] = fr[l + 32 * j];
        } else {
            #pragma unroll
            for (int j = 0; j < 4; j++)
                tile[p * 129 + l + 32 * j] = 0.f;
        }
    }
    __syncthreads();
    int b  = base / PLANE;
    int yx = base - b * PLANE;
    float* outp = out + (size_t)b * ((size_t)D_MODEL * PLANE) + yx + l;
    #pragma unroll
    for (int i = 0; i < 16; i++) {
        int c = (w << 4) | i;
        __stcs(outp + (size_t)c * PLANE, tile[l * 129 + c]);
    }
}

extern "C" void kernel_launch(void* const* d_in, const int* in_sizes, int n_in,
                              void* d_out, int out_size) {
    const float* V   = (const float*)d_in[0];
    const float* W0  = (const float*)d_in[1];
    const float* b0  = (const float*)d_in[2];
    const int*   c32 = (const int*)d_in[3];
    float* out = (float*)d_out;

    cudaFuncSetAttribute((const void*)k_gemm,
                         cudaFuncAttributeMaxDynamicSharedMemorySize, GEMM_SMEM);

    k_setup<<<633, 256>>>(W0);
    k_scatter<<<(N_VOX + 255) / 256, 256>>>(c32);
    k_gemm<<<N_VOX / 64, 256, GEMM_SMEM>>>(V, b0);
    k_gather<<<NPOS / 32, 256>>>(out);
}

// round 9
// speedup vs baseline: 2.4933x; 1.0776x over previous
#include <cuda_runtime.h>
#include <cuda_fp16.h>
#include <cstdint>
#include <cstddef>

#define N_VOX   200000
#define C_IN    128
#define D_MODEL 128
#define NY      400
#define NX      400
#define NB      4
#define PLANE   (NY*NX)        /* 160000 */
#define NPOS    (NB*PLANE)     /* 640000 */

typedef unsigned int u32;

// ---- scratch (device globals; 16B-aligned via vector types) ----
__device__ float4 g_feat4[(size_t)N_VOX * (D_MODEL/4)];   // 102.4 MB
__device__ uint4  g_Wh4[2048];   // 32KB: fp16 image of W0 [n][k] row-major
__device__ int4   g_inv4[NPOS/4];

#define g_feat ((float*)g_feat4)
#define g_inv  ((int*)g_inv4)

__device__ __forceinline__ uint4 round8h(float4 a, float4 b) {
    uint4 hi;
    __half2 h0 = __float22half2_rn(make_float2(a.x, a.y));
    __half2 h1 = __float22half2_rn(make_float2(a.z, a.w));
    __half2 h2 = __float22half2_rn(make_float2(b.x, b.y));
    __half2 h3 = __float22half2_rn(make_float2(b.z, b.w));
    hi.x = *(u32*)&h0; hi.y = *(u32*)&h1; hi.z = *(u32*)&h2; hi.w = *(u32*)&h3;
    return hi;
}

__device__ __forceinline__ u32 smem_u32(const void* p) {
    u32 a;
    asm("{ .reg .u64 t; cvta.to.shared.u64 t, %1; cvt.u32.u64 %0, t; }"
        : "=r"(a) : "l"(p));
    return a;
}
__device__ __forceinline__ void ldsm_x4(u32 addr, u32& r0, u32& r1, u32& r2, u32& r3) {
    asm volatile("ldmatrix.sync.aligned.m8n8.x4.shared.b16 {%0,%1,%2,%3}, [%4];"
                 : "=r"(r0), "=r"(r1), "=r"(r2), "=r"(r3) : "r"(addr));
}
__device__ __forceinline__ void mma16816h(float* c, const u32* a, const u32* b) {
    asm volatile(
        "mma.sync.aligned.m16n8k16.row.col.f32.f16.f16.f32 "
        "{%0,%1,%2,%3}, {%4,%5,%6,%7}, {%8,%9}, {%0,%1,%2,%3};"
        : "+f"(c[0]), "+f"(c[1]), "+f"(c[2]), "+f"(c[3])
        : "r"(a[0]), "r"(a[1]), "r"(a[2]), "r"(a[3]), "r"(b[0]), "r"(b[1]));
}

// ---- kernel 1: setup = init_inv (blocks 0..624) + prep_w (blocks 625..632) ----
__global__ void k_setup(const float* __restrict__ W0) {
    int b = blockIdx.x, t = threadIdx.x;
    if (b < 625) {
        g_inv4[b * 256 + t] = make_int4(-1, -1, -1, -1);   // 160000 int4 exactly
    } else {
        int i = (b - 625) * 256 + t;   // 2048 groups of 8 elems
        const float4* src = (const float4*)(W0 + i * 8);
        g_Wh4[i] = round8h(src[0], src[1]);
    }
}

// ---- kernel 2: scatter with inline per-warp dtype detection ----
// int64 coors as 32-bit words: [b,0, 0,0, y,0, x,0] -> odd words all zero.
__global__ void k_scatter(const int* __restrict__ c32) {
    int l = threadIdx.x & 31;
    int v = c32[8 * l + 3] | c32[8 * l + 7];
    unsigned any = __ballot_sync(0xFFFFFFFF, v != 0);
    bool is64 = (any == 0);
    int n = blockIdx.x * 256 + threadIdx.x;
    if (n >= N_VOX) return;
    int b, y, x;
    if (is64) { b = c32[8*n + 0]; y = c32[8*n + 4]; x = c32[8*n + 6]; }
    else      { b = c32[4*n + 0]; y = c32[4*n + 2]; x = c32[4*n + 3]; }
    g_inv[b * PLANE + y * NX + x] = n;
}

// ---- kernel 3: mma.sync GEMM  feat = Ah @ Wh^T + b0 (single fp16 product)
// A and W both rounded to fp16 (independent error terms ~2.8e-4 each).
// BM=64, 3 CTAs/SM (52KB smem). 8 warps as 2m x 4n. K=128 resident.
// smem tiles stride 136 h16 (272B): ldmatrix banks (4r+c)%32, conflict-free.
#define TSTRIDE 136
#define A_ELEMS (64 * TSTRIDE)    /* 8704 h16 = 17408 B */
#define W_ELEMS (128 * TSTRIDE)   /* 17408 h16 = 34816 B */
#define GEMM_SMEM ((A_ELEMS + W_ELEMS) * 2)   /* 52224 B */

__global__ __launch_bounds__(256, 3) void k_gemm(const float* __restrict__ V,
                                                 const float* __restrict__ b0) {
    extern __shared__ __align__(16) __half sm[];
    __half* Ah = sm;
    __half* Wh = sm + A_ELEMS;

    int tid = threadIdx.x, w = tid >> 5, lane = tid & 31;
    int row_base = blockIdx.x * 64;             // 200000 = 64*3125 exact

    // stage W (32KB fp16, L2-resident pre-rounded image)
    #pragma unroll
    for (int i = 0; i < 8; i++) {
        int x = tid + 256 * i;                  // 2048 uint4
        int n = x >> 4, j = x & 15;
        *(uint4*)(Wh + n * TSTRIDE + 8 * j) = g_Wh4[x];
    }

    // stage A: 1024 groups of 8 floats; fp16 round; evict-first loads
    #pragma unroll
    for (int i = 0; i < 4; i++) {
        int x = tid + 256 * i;
        int r = x >> 4, j = x & 15;             // r: 0..63, cols 8j..8j+7
        const float4* src = (const float4*)(V + (size_t)(row_base + r) * 128 + 8 * j);
        float4 a = __ldcs(src), b = __ldcs(src + 1);
        *(uint4*)(Ah + r * TSTRIDE + 8 * j) = round8h(a, b);
    }
    __syncthreads();

    int wm = w & 1, wn = w >> 1;                // 2m x 4n warp grid
    float acc[2][4][4];
    #pragma unroll
    for (int mt = 0; mt < 2; mt++)
        #pragma unroll
        for (int nt = 0; nt < 4; nt++)
            #pragma unroll
            for (int q = 0; q < 4; q++) acc[mt][nt][q] = 0.f;

    int a_row = 32 * wm + (lane & 15);          // + 16*mt
    int b_row = 32 * wn + (lane & 15);          // + 16*q
    int c_half = (lane >> 4) << 3;              // k offset 0 or 8
    u32 ah_base = smem_u32(Ah), wh_base = smem_u32(Wh);

    #pragma unroll
    for (int ks = 0; ks < 8; ks++) {
        int kb = 16 * ks + c_half;
        u32 aH[2][4], bH[4][2];
        #pragma unroll
        for (int mt = 0; mt < 2; mt++) {
            u32 off = (u32)(((a_row + 16 * mt) * TSTRIDE + kb) * 2);
            ldsm_x4(ah_base + off, aH[mt][0], aH[mt][1], aH[mt][2], aH[mt][3]);
        }
        #pragma unroll
        for (int q = 0; q < 2; q++) {
            u32 off = (u32)(((b_row + 16 * q) * TSTRIDE + kb) * 2);
            u32 r0, r1, r2, r3;
            ldsm_x4(wh_base + off, r0, r1, r2, r3);
            bH[2*q][0] = r0; bH[2*q+1][0] = r1; bH[2*q][1] = r2; bH[2*q+1][1] = r3;
        }
        #pragma unroll
        for (int mt = 0; mt < 2; mt++)
            #pragma unroll
            for (int nt = 0; nt < 4; nt++)
                mma16816h(acc[mt][nt], aH[mt], bH[nt]);
    }

    // epilogue: c-fragment float2 stores + bias (writes allocate in L2)
    int cp = 2 * (lane & 3);
    float2* feat2 = (float2*)g_feat;
    #pragma unroll
    for (int nt = 0; nt < 4; nt++) {
        int c = 32 * wn + 8 * nt + cp;
        float blo = __ldg(b0 + c), bhi = __ldg(b0 + c + 1);
        #pragma unroll
        for (int mt = 0; mt < 2; mt++) {
            int r0 = row_base + 32 * wm + 16 * mt + (lane >> 2);
            feat2[(size_t)r0 * 64 + (c >> 1)] =
                make_float2(acc[mt][nt][0] + blo, acc[mt][nt][1] + bhi);
            feat2[(size_t)(r0 + 8) * 64 + (c >> 1)] =
                make_float2(acc[mt][nt][2] + blo, acc[mt][nt][3] + bhi);
        }
    }
}

// ---- kernel 4: gather + transpose into [B, C, NY, NX] ----
// Block = 128 consecutive positions (PLANE%128==0: never crosses batch).
// Tile [128 ch][stride 132 pos]: phase 1 reads feat rows coalesced (128B)
// and stores float4-over-4-positions (STS.128, banks (4c+p0)+{0..3} over 8
// lanes = all 32, conflict-free); phase 2 LDS.128 conflict-free + 512B
// contiguous STG.128 bursts per warp per channel.
#define GSTRIDE 132
#define GATHER_SMEM (128 * GSTRIDE * 4 + 512)

__global__ __launch_bounds__(256) void k_gather(float* __restrict__ out) {
    extern __shared__ __align__(16) float gsm[];
    float* tileT = gsm;                          // [128 ch][132]
    int*   s_inv = (int*)(gsm + 128 * GSTRIDE);
    int base = blockIdx.x * 128;
    int tid = threadIdx.x, w = tid >> 5, l = tid & 31;
    if (tid < 128) s_inv[tid] = g_inv[base + tid];
    __syncthreads();

    // phase 1: warp w owns positions [16w, 16w+16), in 4 groups of 4
    #pragma unroll
    for (int g = 0; g < 4; g++) {
        int p0 = w * 16 + g * 4;
        float v[4][4];                           // [j: ch chunk][p]
        #pragma unroll
        for (int p = 0; p < 4; p++) {
            int n = s_inv[p0 + p];               // warp-uniform branch
            if (n >= 0) {
                const float* fr = g_feat + (size_t)n * D_MODEL;
                #pragma unroll
                for (int j = 0; j < 4; j++) v[j][p] = fr[l + 32 * j];
            } else {
                #pragma unroll
                for (int j = 0; j < 4; j++) v[j][p] = 0.f;
            }
        }
        #pragma unroll
        for (int j = 0; j < 4; j++) {
            int c = l + 32 * j;
            *(float4*)(tileT + c * GSTRIDE + p0) =
                make_float4(v[j][0], v[j][1], v[j][2], v[j][3]);
        }
    }
    __syncthreads();

    // phase 2: warp w owns channels [16w, 16w+16)
    int b  = base / PLANE;
    int yx = base - b * PLANE;
    float* outp = out + (size_t)b * ((size_t)D_MODEL * PLANE) + yx;
    #pragma unroll
    for (int i = 0; i < 16; i++) {
        int c = w * 16 + i;
        float4 vv = *(float4*)(tileT + c * GSTRIDE + 4 * l);
        __stcs((float4*)(outp + (size_t)c * PLANE + 4 * l), vv);
    }
}

extern "C" void kernel_launch(void* const* d_in, const int* in_sizes, int n_in,
                              void* d_out, int out_size) {
    const float* V   = (const float*)d_in[0];
    const float* W0  = (const float*)d_in[1];
    const float* b0  = (const float*)d_in[2];
    const int*   c32 = (const int*)d_in[3];
    float* out = (float*)d_out;

    cudaFuncSetAttribute((const void*)k_gemm,
                         cudaFuncAttributeMaxDynamicSharedMemorySize, GEMM_SMEM);
    cudaFuncSetAttribute((const void*)k_gather,
                         cudaFuncAttributeMaxDynamicSharedMemorySize, GATHER_SMEM);

    k_setup<<<633, 256>>>(W0);
    k_scatter<<<(N_VOX + 255) / 256, 256>>>(c32);
    k_gemm<<<N_VOX / 64, 256, GEMM_SMEM>>>(V, b0);
    k_gather<<<NPOS / 128, 256, GATHER_SMEM>>>(out);
}